// round 6
// baseline (speedup 1.0000x reference)
#include <cuda_runtime.h>
#include <cuda_bf16.h>
#include <math.h>

#define BB 2
#define SS 2048
#define DD 1024
#define HH 16
#define DHH 64

// ---------------- scratch ----------------
__device__ __nv_bfloat16 g_qh_h[BB*HH*SS*DHH];
__device__ __nv_bfloat16 g_qh_l[BB*HH*SS*DHH];
__device__ __nv_bfloat16 g_kh_h[BB*HH*SS*DHH];
__device__ __nv_bfloat16 g_kh_l[BB*HH*SS*DHH];
__device__ __nv_bfloat16 g_vT_h[BB*DHH*SS];   // [b, e, t]
__device__ __nv_bfloat16 g_vT_l[BB*DHH*SS];
__device__ float g_oh[BB*HH*SS*DHH];
__device__ float g_mean[BB*SS*DHH];
__device__ float g_m[BB*HH*SS];
__device__ float g_l[BB*HH*SS];

// ---------------- helpers ----------------
__device__ __forceinline__ unsigned smem_u32(const void* p) {
    unsigned a;
    asm("{ .reg .u64 t; cvta.to.shared.u64 t, %1; cvt.u32.u64 %0, t; }" : "=r"(a) : "l"(p));
    return a;
}

__device__ __forceinline__ void sts64(unsigned addr, unsigned long long v) {
    asm volatile("st.shared.b64 [%0], %1;" :: "r"(addr), "l"(v) : "memory");
}

__device__ __forceinline__ void ldsm4(unsigned addr, unsigned& r0, unsigned& r1,
                                      unsigned& r2, unsigned& r3) {
    asm volatile("ldmatrix.sync.aligned.m8n8.x4.shared.b16 {%0,%1,%2,%3}, [%4];"
        : "=r"(r0), "=r"(r1), "=r"(r2), "=r"(r3) : "r"(addr));
}

__device__ __forceinline__ void mma16816(float* c, const unsigned* a, const unsigned* b) {
    asm volatile("mma.sync.aligned.m16n8k16.row.col.f32.bf16.bf16.f32 "
        "{%0,%1,%2,%3}, {%4,%5,%6,%7}, {%8,%9}, {%0,%1,%2,%3};"
        : "+f"(c[0]), "+f"(c[1]), "+f"(c[2]), "+f"(c[3])
        : "r"(a[0]), "r"(a[1]), "r"(a[2]), "r"(a[3]), "r"(b[0]), "r"(b[1]));
}

__device__ __forceinline__ void split2(float a, float b, unsigned& hi, unsigned& lo) {
    __nv_bfloat162 h = __float22bfloat162_rn(make_float2(a, b));
    float2 hf = __bfloat1622float2(h);
    __nv_bfloat162 l = __float22bfloat162_rn(make_float2(a - hf.x, b - hf.y));
    hi = *(unsigned*)&h; lo = *(unsigned*)&l;
}

// rows x 64 fp32 (row stride ld elems, col offset k0) -> split -> smem hi/lo, 144B row stride
__device__ __forceinline__ void load_f32_split(const float* __restrict__ src, int rows,
                                               size_t ld, int k0, unsigned sh, unsigned sl,
                                               int tid, int nthr) {
    int nch = rows * 16;
    for (int c = tid; c < nch; c += nthr) {
        int row = c >> 4, cg = c & 15;
        float4 f = *(const float4*)&src[(size_t)row * ld + k0 + cg * 4];
        unsigned h0, l0, h1, l1;
        split2(f.x, f.y, h0, l0);
        split2(f.z, f.w, h1, l1);
        unsigned off = (unsigned)(row * 144 + cg * 8);
        sts64(sh + off, ((unsigned long long)h1 << 32) | h0);
        sts64(sl + off, ((unsigned long long)l1 << 32) | l0);
    }
}

// rows x 64 bf16 (contiguous rows of 64) -> smem, 144B row stride
__device__ __forceinline__ void load_bf16_pair(const __nv_bfloat16* __restrict__ srcH,
                                               const __nv_bfloat16* __restrict__ srcL,
                                               int rows, unsigned sh, unsigned sl,
                                               int tid, int nthr) {
    const unsigned long long* pH = (const unsigned long long*)srcH;
    const unsigned long long* pL = (const unsigned long long*)srcL;
    int nch = rows * 16;
    for (int c = tid; c < nch; c += nthr) {
        int row = c >> 4, cg = c & 15;
        unsigned off = (unsigned)(row * 144 + cg * 8);
        sts64(sh + off, pH[c]);
        sts64(sl + off, pL[c]);
    }
}

// 64 x 64 bf16, row stride ld elems, col offset t0 -> smem, 144B row stride
__device__ __forceinline__ void load_bf16_strided(const __nv_bfloat16* __restrict__ srcH,
                                                  const __nv_bfloat16* __restrict__ srcL,
                                                  size_t ld, int t0, unsigned sh, unsigned sl,
                                                  int tid, int nthr) {
    for (int c = tid; c < 64 * 16; c += nthr) {
        int row = c >> 4, cg = c & 15;
        unsigned long long h = *(const unsigned long long*)&srcH[(size_t)row * ld + t0 + cg * 4];
        unsigned long long l = *(const unsigned long long*)&srcL[(size_t)row * ld + t0 + cg * 4];
        unsigned off = (unsigned)(row * 144 + cg * 8);
        sts64(sh + off, h);
        sts64(sl + off, l);
    }
}

// ---------------- kernel 1: projections (HMMA) ----------------
__global__ __launch_bounds__(256) void proj_mma(
    const float* __restrict__ q, const float* __restrict__ k, const float* __restrict__ v,
    const float* __restrict__ Wq, const float* __restrict__ bq,
    const float* __restrict__ Wk, const float* __restrict__ bk,
    const float* __restrict__ Wv, const float* __restrict__ bv)
{
    extern __shared__ char sm_[];
    unsigned sb = smem_u32(sm_);
    const unsigned AH = sb, AL = sb + 18432, BH = sb + 36864, BL = sb + 46080;

    int tid = threadIdx.x, w = tid >> 5, lane = tid & 31;
    int mt = blockIdx.x, b = blockIdx.y, task = blockIdx.z;
    int s0 = mt * 128;

    const float *X, *W, *bias;
    __nv_bfloat16 *dstH = 0, *dstL = 0;
    int isV = 0;
    if (task < HH) {
        X = q + (size_t)b*SS*DD; W = Wq + (size_t)task*DHH*DD; bias = bq + task*DHH;
        dstH = g_qh_h + (size_t)(b*HH + task)*SS*DHH;
        dstL = g_qh_l + (size_t)(b*HH + task)*SS*DHH;
    } else if (task < 2*HH) {
        int h = task - HH;
        X = k + (size_t)b*SS*DD; W = Wk + (size_t)h*DHH*DD; bias = bk + h*DHH;
        dstH = g_kh_h + (size_t)(b*HH + h)*SS*DHH;
        dstL = g_kh_l + (size_t)(b*HH + h)*SS*DHH;
    } else {
        X = v + (size_t)b*SS*DD; W = Wv; bias = bv; isV = 1;
    }

    float cf[8][4];
    #pragma unroll
    for (int nf = 0; nf < 8; nf++)
        #pragma unroll
        for (int i = 0; i < 4; i++) cf[nf][i] = 0.f;

    int lrow = lane & 15;
    unsigned lcol16 = (unsigned)(lane >> 4) * 16;
    unsigned aBaseH = AH + (unsigned)(16*w + lrow) * 144 + lcol16;
    unsigned aBaseL = AL + (unsigned)(16*w + lrow) * 144 + lcol16;

    for (int c = 0; c < 16; c++) {
        __syncthreads();
        load_f32_split(X + (size_t)s0 * DD, 128, DD, c * 64, AH, AL, tid, 256);
        load_f32_split(W, 64, DD, c * 64, BH, BL, tid, 256);
        __syncthreads();
        #pragma unroll
        for (int ks = 0; ks < 4; ks++) {
            unsigned kb = (unsigned)ks * 32;
            unsigned aH[4], aL[4];
            ldsm4(aBaseH + kb, aH[0], aH[1], aH[2], aH[3]);
            ldsm4(aBaseL + kb, aL[0], aL[1], aL[2], aL[3]);
            unsigned bh[8][2], bl[8][2];
            #pragma unroll
            for (int nt2 = 0; nt2 < 4; nt2++) {
                unsigned r0, r1, r2, r3;
                unsigned boff = (unsigned)(nt2*16 + lrow) * 144 + lcol16 + kb;
                ldsm4(BH + boff, r0, r1, r2, r3);
                bh[2*nt2][0] = r0; bh[2*nt2][1] = r2;
                bh[2*nt2+1][0] = r1; bh[2*nt2+1][1] = r3;
                ldsm4(BL + boff, r0, r1, r2, r3);
                bl[2*nt2][0] = r0; bl[2*nt2][1] = r2;
                bl[2*nt2+1][0] = r1; bl[2*nt2+1][1] = r3;
            }
            #pragma unroll
            for (int nf = 0; nf < 8; nf++) {
                mma16816(cf[nf], aH, bh[nf]);
                mma16816(cf[nf], aH, bl[nf]);
                mma16816(cf[nf], aL, bh[nf]);
            }
        }
    }

    int row0 = s0 + 16*w + (lane >> 2);
    int colb = (lane & 3) * 2;
    if (!isV) {
        #pragma unroll
        for (int nf = 0; nf < 8; nf++) {
            int col = nf * 8 + colb;
            float b0 = __ldg(&bias[col]), b1 = __ldg(&bias[col + 1]);
            unsigned h, l;
            split2(cf[nf][0] + b0, cf[nf][1] + b1, h, l);
            *(unsigned*)&dstH[(size_t)row0 * DHH + col] = h;
            *(unsigned*)&dstL[(size_t)row0 * DHH + col] = l;
            split2(cf[nf][2] + b0, cf[nf][3] + b1, h, l);
            *(unsigned*)&dstH[(size_t)(row0 + 8) * DHH + col] = h;
            *(unsigned*)&dstL[(size_t)(row0 + 8) * DHH + col] = l;
        }
    } else {
        #pragma unroll
        for (int nf = 0; nf < 8; nf++) {
            int col = nf * 8 + colb;
            float b0 = __ldg(&bias[col]), b1 = __ldg(&bias[col + 1]);
            float vv[4] = {cf[nf][0] + b0, cf[nf][1] + b1, cf[nf][2] + b0, cf[nf][3] + b1};
            int rr[4] = {row0, row0, row0 + 8, row0 + 8};
            int cc[4] = {col, col + 1, col, col + 1};
            #pragma unroll
            for (int i = 0; i < 4; i++) {
                __nv_bfloat16 hb = __float2bfloat16(vv[i]);
                __nv_bfloat16 lb = __float2bfloat16(vv[i] - __bfloat162float(hb));
                g_vT_h[((size_t)b * DHH + cc[i]) * SS + rr[i]] = hb;
                g_vT_l[((size_t)b * DHH + cc[i]) * SS + rr[i]] = lb;
            }
        }
    }
}

// ---------------- kernel 2: flash attention (online softmax + PV, stats out) ----------------
// per CTA: 128 q-rows, loop over 64-wide K/V tiles. warp w owns rows [16w,16w+16).
__global__ __launch_bounds__(256) void flash_mma()
{
    int mt = (int)(gridDim.x - 1 - blockIdx.x);   // big tiles first
    int h = blockIdx.y, b = blockIdx.z;
    int m0 = mt * 128;
    int tid = threadIdx.x, w = tid >> 5, lane = tid & 31;

    extern __shared__ char sm_[];
    unsigned sb = smem_u32(sm_);
    const unsigned QH = sb,         QL = sb + 18432;
    const unsigned KH = sb + 36864, KL = sb + 46080;
    const unsigned VH = sb + 55296, VL = sb + 64512;

    size_t bh = (size_t)(b*HH + h);
    load_bf16_pair(g_qh_h + (bh*SS + m0)*DHH, g_qh_l + (bh*SS + m0)*DHH, 128, QH, QL, tid, 256);

    int lrow = lane & 15;
    unsigned lcol16 = (unsigned)(lane >> 4) * 16;
    int grp = lane >> 2, tig = lane & 3;
    int r0 = m0 + 16*w + grp, r1 = r0 + 8;
    int rmin = m0 + 16*w, rmax = rmin + 15;
    unsigned aoffBase = (unsigned)(16*w + lrow) * 144 + lcol16;

    float mr[2] = {-INFINITY, -INFINITY};
    float lr[2] = {0.f, 0.f};
    float acc[8][4];
    #pragma unroll
    for (int nf = 0; nf < 8; nf++)
        #pragma unroll
        for (int i = 0; i < 4; i++) acc[nf][i] = 0.f;

    int jmax = (m0 + 127) >> 6;
    for (int j = 0; j <= jmax; j++) {
        int t0 = j * 64;
        __syncthreads();
        load_bf16_pair(g_kh_h + (bh*SS + t0)*DHH, g_kh_l + (bh*SS + t0)*DHH, 64, KH, KL, tid, 256);
        load_bf16_strided(g_vT_h + (size_t)b*DHH*SS, g_vT_l + (size_t)b*DHH*SS, SS, t0, VH, VL, tid, 256);
        __syncthreads();
        if (t0 > rmax) continue;

        float cf[8][4];
        #pragma unroll
        for (int nf = 0; nf < 8; nf++)
            #pragma unroll
            for (int i = 0; i < 4; i++) cf[nf][i] = 0.f;

        // ---- scores: Q(128x64) x K(64x64)^T, split 3-term ----
        #pragma unroll
        for (int kb4 = 0; kb4 < 4; kb4++) {
            unsigned kb = (unsigned)kb4 * 32;
            unsigned aH[4], aL[4];
            ldsm4(QH + aoffBase + kb, aH[0], aH[1], aH[2], aH[3]);
            ldsm4(QL + aoffBase + kb, aL[0], aL[1], aL[2], aL[3]);
            #pragma unroll
            for (int nt2 = 0; nt2 < 4; nt2++) {
                unsigned boff = (unsigned)(nt2*16 + lrow) * 144 + lcol16 + kb;
                unsigned x0, x1, x2, x3;
                unsigned bhf[2][2], blf[2][2];
                ldsm4(KH + boff, x0, x1, x2, x3);
                bhf[0][0] = x0; bhf[0][1] = x2; bhf[1][0] = x1; bhf[1][1] = x3;
                ldsm4(KL + boff, x0, x1, x2, x3);
                blf[0][0] = x0; blf[0][1] = x2; blf[1][0] = x1; blf[1][1] = x3;
                mma16816(cf[2*nt2],   aH, bhf[0]);
                mma16816(cf[2*nt2],   aH, blf[0]);
                mma16816(cf[2*nt2],   aL, bhf[0]);
                mma16816(cf[2*nt2+1], aH, bhf[1]);
                mma16816(cf[2*nt2+1], aH, blf[1]);
                mma16816(cf[2*nt2+1], aL, bhf[1]);
            }
        }

        // ---- scale + causal mask ----
        if (t0 + 63 <= rmin) {
            #pragma unroll
            for (int nf = 0; nf < 8; nf++)
                #pragma unroll
                for (int i = 0; i < 4; i++) cf[nf][i] *= 0.125f;
        } else {
            #pragma unroll
            for (int nf = 0; nf < 8; nf++)
                #pragma unroll
                for (int i = 0; i < 4; i++) {
                    int col = t0 + nf*8 + tig*2 + (i & 1);
                    int row = (i < 2) ? r0 : r1;
                    cf[nf][i] = (col <= row) ? cf[nf][i] * 0.125f : -INFINITY;
                }
        }

        // ---- online stats ----
        float mx0 = -INFINITY, mx1 = -INFINITY;
        #pragma unroll
        for (int nf = 0; nf < 8; nf++) {
            mx0 = fmaxf(mx0, fmaxf(cf[nf][0], cf[nf][1]));
            mx1 = fmaxf(mx1, fmaxf(cf[nf][2], cf[nf][3]));
        }
        mx0 = fmaxf(mx0, __shfl_xor_sync(0xffffffffu, mx0, 1));
        mx0 = fmaxf(mx0, __shfl_xor_sync(0xffffffffu, mx0, 2));
        mx1 = fmaxf(mx1, __shfl_xor_sync(0xffffffffu, mx1, 1));
        mx1 = fmaxf(mx1, __shfl_xor_sync(0xffffffffu, mx1, 2));

        float mn0 = fmaxf(mr[0], mx0), mn1 = fmaxf(mr[1], mx1);
        float fac0 = __expf(mr[0] - mn0), fac1 = __expf(mr[1] - mn1);
        mr[0] = mn0; mr[1] = mn1;

        float s0 = 0.f, s1 = 0.f;
        #pragma unroll
        for (int nf = 0; nf < 8; nf++) {
            cf[nf][0] = __expf(cf[nf][0] - mn0); s0 += cf[nf][0];
            cf[nf][1] = __expf(cf[nf][1] - mn0); s0 += cf[nf][1];
            cf[nf][2] = __expf(cf[nf][2] - mn1); s1 += cf[nf][2];
            cf[nf][3] = __expf(cf[nf][3] - mn1); s1 += cf[nf][3];
        }
        s0 += __shfl_xor_sync(0xffffffffu, s0, 1);
        s0 += __shfl_xor_sync(0xffffffffu, s0, 2);
        s1 += __shfl_xor_sync(0xffffffffu, s1, 1);
        s1 += __shfl_xor_sync(0xffffffffu, s1, 2);
        lr[0] = lr[0] * fac0 + s0;
        lr[1] = lr[1] * fac1 + s1;

        #pragma unroll
        for (int nf = 0; nf < 8; nf++) {
            acc[nf][0] *= fac0; acc[nf][1] *= fac0;
            acc[nf][2] *= fac1; acc[nf][3] *= fac1;
        }

        // ---- PV: P(128x64) x V(64x64)^T — P from registers (C->A frag identity) ----
        #pragma unroll
        for (int kk = 0; kk < 4; kk++) {
            unsigned aP[4], aQ[4];
            split2(cf[2*kk][0],   cf[2*kk][1],   aP[0], aQ[0]);
            split2(cf[2*kk][2],   cf[2*kk][3],   aP[1], aQ[1]);
            split2(cf[2*kk+1][0], cf[2*kk+1][1], aP[2], aQ[2]);
            split2(cf[2*kk+1][2], cf[2*kk+1][3], aP[3], aQ[3]);
            unsigned kb = (unsigned)kk * 32;
            #pragma unroll
            for (int nt2 = 0; nt2 < 4; nt2++) {
                unsigned boff = (unsigned)(nt2*16 + lrow) * 144 + lcol16 + kb;
                unsigned x0, x1, x2, x3;
                unsigned bvh[2][2], bvl[2][2];
                ldsm4(VH + boff, x0, x1, x2, x3);
                bvh[0][0] = x0; bvh[0][1] = x2; bvh[1][0] = x1; bvh[1][1] = x3;
                ldsm4(VL + boff, x0, x1, x2, x3);
                bvl[0][0] = x0; bvl[0][1] = x2; bvl[1][0] = x1; bvl[1][1] = x3;
                mma16816(acc[2*nt2],   aP, bvh[0]);
                mma16816(acc[2*nt2],   aP, bvl[0]);
                mma16816(acc[2*nt2],   aQ, bvh[0]);
                mma16816(acc[2*nt2+1], aP, bvh[1]);
                mma16816(acc[2*nt2+1], aP, bvl[1]);
                mma16816(acc[2*nt2+1], aQ, bvh[1]);
            }
        }
    }

    // ---- epilogue ----
    float inv0 = 1.f / lr[0], inv1 = 1.f / lr[1];
    float* dst = g_oh + bh * SS * DHH;
    #pragma unroll
    for (int nf = 0; nf < 8; nf++) {
        int col = nf * 8 + tig * 2;
        *(float2*)&dst[(size_t)r0 * DHH + col] = make_float2(acc[nf][0]*inv0, acc[nf][1]*inv0);
        *(float2*)&dst[(size_t)r1 * DHH + col] = make_float2(acc[nf][2]*inv1, acc[nf][3]*inv1);
    }
    if (tig == 0) {
        g_m[bh*SS + r0] = mr[0]; g_l[bh*SS + r0] = lr[0];
        g_m[bh*SS + r1] = mr[1]; g_l[bh*SS + r1] = lr[1];
    }
}

// ---------------- kernel 3: recompute scores, normalize with stats, write attn ----------------
__global__ __launch_bounds__(256) void scorewrite_mma(float* __restrict__ attn)
{
    int x = blockIdx.x;
    int mt = x >> 4, nt = x & 15;
    int h = blockIdx.y, b = blockIdx.z;
    int m0 = mt * 128, n0 = nt * 128;
    int tid = threadIdx.x, w = tid >> 5, lane = tid & 31;
    size_t bh = (size_t)(b * HH + h);
    float* dstBase = attn + (((size_t)b * SS + m0) * HH + h) * SS + n0;

    if (nt > mt) {   // upper triangle: zeros
        float4 z = make_float4(0.f, 0.f, 0.f, 0.f);
        #pragma unroll
        for (int i = 0; i < 16; i++) {
            int fid = (tid + i * 256) * 4;
            int row = fid >> 7, col = fid & 127;
            *(float4*)(dstBase + (size_t)row * HH * SS + col) = z;
        }
        return;
    }

    extern __shared__ char sm_[];
    unsigned sb = smem_u32(sm_);
    const unsigned QH = sb, QL = sb + 18432, KH = sb + 36864, KL = sb + 55296;
    float* sm_m  = (float*)(sm_ + 73728);
    float* sm_il = sm_m + 128;

    if (tid < 128) {
        sm_m[tid]  = g_m[bh*SS + m0 + tid];
        sm_il[tid] = 1.f / g_l[bh*SS + m0 + tid];
    }
    load_bf16_pair(g_qh_h + (bh*SS + m0)*DHH, g_qh_l + (bh*SS + m0)*DHH, 128, QH, QL, tid, 256);
    load_bf16_pair(g_kh_h + (bh*SS + n0)*DHH, g_kh_l + (bh*SS + n0)*DHH, 128, KH, KL, tid, 256);
    __syncthreads();

    int mw = w >> 1, nw = w & 1;     // warp tile: 32 rows x 64 cols
    int lrow = lane & 15;
    unsigned lcol16 = (unsigned)(lane >> 4) * 16;
    int grp = lane >> 2, tig = lane & 3;

    float cf[2][8][4];
    #pragma unroll
    for (int mf = 0; mf < 2; mf++)
        #pragma unroll
        for (int nf = 0; nf < 8; nf++)
            #pragma unroll
            for (int i = 0; i < 4; i++) cf[mf][nf][i] = 0.f;

    #pragma unroll
    for (int ks = 0; ks < 4; ks++) {
        unsigned kb = (unsigned)ks * 32;
        unsigned aH[2][4], aL[2][4];
        #pragma unroll
        for (int mf = 0; mf < 2; mf++) {
            unsigned aoff = (unsigned)(mw*32 + mf*16 + lrow) * 144 + lcol16 + kb;
            ldsm4(QH + aoff, aH[mf][0], aH[mf][1], aH[mf][2], aH[mf][3]);
            ldsm4(QL + aoff, aL[mf][0], aL[mf][1], aL[mf][2], aL[mf][3]);
        }
        unsigned bh2[8][2], bl2[8][2];
        #pragma unroll
        for (int nt2 = 0; nt2 < 4; nt2++) {
            unsigned boff = (unsigned)(nw*64 + nt2*16 + lrow) * 144 + lcol16 + kb;
            unsigned x0, x1, x2, x3;
            ldsm4(KH + boff, x0, x1, x2, x3);
            bh2[2*nt2][0] = x0; bh2[2*nt2][1] = x2;
            bh2[2*nt2+1][0] = x1; bh2[2*nt2+1][1] = x3;
            ldsm4(KL + boff, x0, x1, x2, x3);
            bl2[2*nt2][0] = x0; bl2[2*nt2][1] = x2;
            bl2[2*nt2+1][0] = x1; bl2[2*nt2+1][1] = x3;
        }
        #pragma unroll
        for (int mf = 0; mf < 2; mf++)
            #pragma unroll
            for (int nf = 0; nf < 8; nf++) {
                mma16816(cf[mf][nf], aH[mf], bh2[nf]);
                mma16816(cf[mf][nf], aH[mf], bl2[nf]);
                mma16816(cf[mf][nf], aL[mf], bh2[nf]);
            }
    }

    // normalize: p = exp(raw/8 - m) / l, diag mask
    bool diag = (nt == mt);
    #pragma unroll
    for (int mf = 0; mf < 2; mf++) {
        int rl0 = mw*32 + mf*16 + grp;
        float m0v = sm_m[rl0],     il0 = sm_il[rl0];
        float m1v = sm_m[rl0 + 8], il1 = sm_il[rl0 + 8];
        #pragma unroll
        for (int nf = 0; nf < 8; nf++) {
            #pragma unroll
            for (int i = 0; i < 4; i++) {
                float mm = (i < 2) ? m0v : m1v;
                float il = (i < 2) ? il0 : il1;
                float p = __expf(cf[mf][nf][i] * 0.125f - mm) * il;
                if (diag) {
                    int rowg = m0 + rl0 + ((i < 2) ? 0 : 8);
                    int colg = n0 + nw*64 + nf*8 + tig*2 + (i & 1);
                    if (colg > rowg) p = 0.f;
                }
                cf[mf][nf][i] = p;
            }
        }
    }

    // stage through smem for coalesced writes
    __syncthreads();
    int rbase = mw * 32 + grp;
    int cbase = nw * 64 + tig * 2;
    #pragma unroll
    for (int mf = 0; mf < 2; mf++)
        #pragma unroll
        for (int nf = 0; nf < 8; nf++) {
            int r = rbase + mf * 16, c = cbase + nf * 8;
            *(float2*)(sm_ + ((size_t)r * 132 + c) * 4) = make_float2(cf[mf][nf][0], cf[mf][nf][1]);
            *(float2*)(sm_ + ((size_t)(r + 8) * 132 + c) * 4) = make_float2(cf[mf][nf][2], cf[mf][nf][3]);
        }
    __syncthreads();

    #pragma unroll
    for (int i = 0; i < 16; i++) {
        int fid = (tid + i * 256) * 4;
        int row = fid >> 7, col = fid & 127;
        float4 f = *(const float4*)(sm_ + ((size_t)row * 132 + col) * 4);
        *(float4*)(dstBase + (size_t)row * HH * SS + col) = f;
    }
}

// ---------------- kernel 4: mean over heads ----------------
__global__ __launch_bounds__(256) void mean_kernel()
{
    int idx = blockIdx.x * 256 + threadIdx.x;
    int e = idx & 63;
    int s = (idx >> 6) & (SS - 1);
    int b = idx >> 17;
    float sum = 0.f;
    #pragma unroll
    for (int h = 0; h < HH; h++)
        sum += g_oh[((size_t)(b*HH + h)*SS + s)*DHH + e];
    g_mean[idx] = sum * (1.f / 16.f);
}

// ---------------- kernel 5: output projection ----------------
__global__ __launch_bounds__(256) void outproj_kernel(const float* __restrict__ Wo,
                                                      float* __restrict__ out)
{
    __shared__ float ms[64][68];
    __shared__ float wsm[64][68];
    int s0 = blockIdx.x * 64, d0 = blockIdx.y * 64, b = blockIdx.z;
    int tid = threadIdx.x;
    int ty = tid >> 4, tx = tid & 15;
    int lr = tid >> 2;
    int le = (tid & 3) * 16;

    #pragma unroll
    for (int i = 0; i < 16; i += 4) {
        float4 f = *(const float4*)&g_mean[((size_t)b*SS + s0+lr)*DHH + le + i];
        ms[le+i+0][lr] = f.x; ms[le+i+1][lr] = f.y;
        ms[le+i+2][lr] = f.z; ms[le+i+3][lr] = f.w;
        float4 g = *(const float4*)&Wo[(size_t)(d0+lr)*DHH + le + i];
        wsm[le+i+0][lr] = g.x; wsm[le+i+1][lr] = g.y;
        wsm[le+i+2][lr] = g.z; wsm[le+i+3][lr] = g.w;
    }
    __syncthreads();

    float acc[4][4];
    #pragma unroll
    for (int i = 0; i < 4; i++)
        #pragma unroll
        for (int j = 0; j < 4; j++) acc[i][j] = 0.f;

    #pragma unroll 16
    for (int e = 0; e < 64; e++) {
        float4 mf = *(const float4*)&ms[e][ty*4];
        float4 wf = *(const float4*)&wsm[e][tx*4];
        float mr[4] = {mf.x, mf.y, mf.z, mf.w};
        float wr[4] = {wf.x, wf.y, wf.z, wf.w};
        #pragma unroll
        for (int i = 0; i < 4; i++)
            #pragma unroll
            for (int j = 0; j < 4; j++)
                acc[i][j] += mr[i] * wr[j];
    }

    #pragma unroll
    for (int i = 0; i < 4; i++) {
        float4 o;
        o.x = acc[i][0]; o.y = acc[i][1]; o.z = acc[i][2]; o.w = acc[i][3];
        *(float4*)&out[(size_t)b*SS*DD + (size_t)(s0 + ty*4 + i)*DD + d0 + tx*4] = o;
    }
}

// ---------------- launch ----------------
extern "C" void kernel_launch(void* const* d_in, const int* in_sizes, int n_in,
                              void* d_out, int out_size)
{
    (void)in_sizes; (void)n_in; (void)out_size;
    const float* q  = (const float*)d_in[0];
    const float* k  = (const float*)d_in[1];
    const float* v  = (const float*)d_in[2];
    const float* Wv = (const float*)d_in[4];
    const float* bv = (const float*)d_in[5];
    const float* Wq = (const float*)d_in[6];
    const float* bq = (const float*)d_in[7];
    const float* Wk = (const float*)d_in[8];
    const float* bk = (const float*)d_in[9];
    const float* Wo = (const float*)d_in[10];

    float* out  = (float*)d_out;
    float* attn = out + (size_t)BB*SS*DD;

    const int PROJ_SMEM   = 55296;
    const int FLASH_SMEM  = 73728;
    const int SCOREW_SMEM = 74752;

    cudaFuncSetAttribute(proj_mma,       cudaFuncAttributeMaxDynamicSharedMemorySize, PROJ_SMEM);
    cudaFuncSetAttribute(flash_mma,      cudaFuncAttributeMaxDynamicSharedMemorySize, FLASH_SMEM);
    cudaFuncSetAttribute(scorewrite_mma, cudaFuncAttributeMaxDynamicSharedMemorySize, SCOREW_SMEM);

    proj_mma<<<dim3(SS/128, BB, 2*HH + 1), 256, PROJ_SMEM>>>(q, k, v, Wq, bq, Wk, bk, Wv, bv);
    flash_mma<<<dim3(SS/128, HH, BB), 256, FLASH_SMEM>>>();
    scorewrite_mma<<<dim3(256, HH, BB), 256, SCOREW_SMEM>>>(attn);
    mean_kernel<<<BB*SS*DHH/256, 256>>>();
    outproj_kernel<<<dim3(SS/64, DD/64, BB), 256>>>(Wo, out);
}

// round 8
// speedup vs baseline: 1.4038x; 1.4038x over previous
#include <cuda_runtime.h>
#include <cuda_bf16.h>
#include <math.h>

#define BB 2
#define SS 2048
#define DD 1024
#define HH 16
#define DHH 64

// ---------------- scratch ----------------
__device__ __nv_bfloat16 g_qh_h[BB*HH*SS*DHH];
__device__ __nv_bfloat16 g_qh_l[BB*HH*SS*DHH];
__device__ __nv_bfloat16 g_kh_h[BB*HH*SS*DHH];
__device__ __nv_bfloat16 g_kh_l[BB*HH*SS*DHH];
__device__ __nv_bfloat16 g_vT_h[BB*DHH*SS];   // [b, e, t]
__device__ __nv_bfloat16 g_vT_l[BB*DHH*SS];
__device__ float g_oh[BB*HH*SS*DHH];
__device__ float g_mean[BB*SS*DHH];

// ---------------- helpers ----------------
__device__ __forceinline__ unsigned smem_u32(const void* p) {
    unsigned a;
    asm("{ .reg .u64 t; cvta.to.shared.u64 t, %1; cvt.u32.u64 %0, t; }" : "=r"(a) : "l"(p));
    return a;
}

__device__ __forceinline__ void sts64(unsigned addr, unsigned long long v) {
    asm volatile("st.shared.b64 [%0], %1;" :: "r"(addr), "l"(v) : "memory");
}

__device__ __forceinline__ void ldsm4(unsigned addr, unsigned& r0, unsigned& r1,
                                      unsigned& r2, unsigned& r3) {
    asm volatile("ldmatrix.sync.aligned.m8n8.x4.shared.b16 {%0,%1,%2,%3}, [%4];"
        : "=r"(r0), "=r"(r1), "=r"(r2), "=r"(r3) : "r"(addr));
}

__device__ __forceinline__ void mma16816(float* c, const unsigned* a, const unsigned* b) {
    asm volatile("mma.sync.aligned.m16n8k16.row.col.f32.bf16.bf16.f32 "
        "{%0,%1,%2,%3}, {%4,%5,%6,%7}, {%8,%9}, {%0,%1,%2,%3};"
        : "+f"(c[0]), "+f"(c[1]), "+f"(c[2]), "+f"(c[3])
        : "r"(a[0]), "r"(a[1]), "r"(a[2]), "r"(a[3]), "r"(b[0]), "r"(b[1]));
}

__device__ __forceinline__ void split2(float a, float b, unsigned& hi, unsigned& lo) {
    __nv_bfloat162 h = __float22bfloat162_rn(make_float2(a, b));
    float2 hf = __bfloat1622float2(h);
    __nv_bfloat162 l = __float22bfloat162_rn(make_float2(a - hf.x, b - hf.y));
    hi = *(unsigned*)&h; lo = *(unsigned*)&l;
}

__device__ __forceinline__ void cp16(unsigned dst, const void* src) {
    asm volatile("cp.async.cg.shared.global [%0], [%1], 16;" :: "r"(dst), "l"(src));
}
#define CP_COMMIT() asm volatile("cp.async.commit_group;")
#define CP_WAIT0()  asm volatile("cp.async.wait_group 0;")

// rows x 64 bf16 (contiguous rows of 64) -> smem, 144B row stride
__device__ __forceinline__ void load_bf16_pair(const __nv_bfloat16* __restrict__ srcH,
                                               const __nv_bfloat16* __restrict__ srcL,
                                               int rows, unsigned sh, unsigned sl,
                                               int tid, int nthr) {
    const unsigned long long* pH = (const unsigned long long*)srcH;
    const unsigned long long* pL = (const unsigned long long*)srcL;
    int nch = rows * 16;
    for (int c = tid; c < nch; c += nthr) {
        int row = c >> 4, cg = c & 15;
        unsigned off = (unsigned)(row * 144 + cg * 8);
        sts64(sh + off, pH[c]);
        sts64(sl + off, pL[c]);
    }
}

#define STG 55296   // stage stride (AH 0, AL 18432, BH 36864, BL 46080)

// ---------------- kernel 1: projections (HMMA, double-buffered) ----------------
// out[s,e] = sum_d X[s,d]*W[e,d] + bias[e]; block: M=128, N=64, K=1024 in 16 chunks
__global__ __launch_bounds__(256) void proj_mma(
    const float* __restrict__ q, const float* __restrict__ k, const float* __restrict__ v,
    const float* __restrict__ Wq, const float* __restrict__ bq,
    const float* __restrict__ Wk, const float* __restrict__ bk,
    const float* __restrict__ Wv, const float* __restrict__ bv)
{
    extern __shared__ char sm_[];
    unsigned sb = smem_u32(sm_);

    int tid = threadIdx.x, w = tid >> 5, lane = tid & 31;
    int mt = blockIdx.x, b = blockIdx.y, task = blockIdx.z;
    int s0 = mt * 128;

    const float *X, *W, *bias;
    __nv_bfloat16 *dstH = 0, *dstL = 0;
    int isV = 0;
    if (task < HH) {
        X = q + (size_t)b*SS*DD; W = Wq + (size_t)task*DHH*DD; bias = bq + task*DHH;
        dstH = g_qh_h + (size_t)(b*HH + task)*SS*DHH;
        dstL = g_qh_l + (size_t)(b*HH + task)*SS*DHH;
    } else if (task < 2*HH) {
        int h = task - HH;
        X = k + (size_t)b*SS*DD; W = Wk + (size_t)h*DHH*DD; bias = bk + h*DHH;
        dstH = g_kh_h + (size_t)(b*HH + h)*SS*DHH;
        dstL = g_kh_l + (size_t)(b*HH + h)*SS*DHH;
    } else {
        X = v + (size_t)b*SS*DD; W = Wv; bias = bv; isV = 1;
    }
    const float* Xb = X + (size_t)s0 * DD;

    float cf[8][4];
    #pragma unroll
    for (int nf = 0; nf < 8; nf++)
        #pragma unroll
        for (int i = 0; i < 4; i++) cf[nf][i] = 0.f;

    int lrow = lane & 15;
    unsigned lcol16 = (unsigned)(lane >> 4) * 16;

    float4 xr[8], wr[4];

    // prologue: load chunk 0
    #pragma unroll
    for (int i = 0; i < 8; i++) {
        int idx = tid + i*256; int row = idx >> 4, cg = idx & 15;
        xr[i] = *(const float4*)&Xb[(size_t)row * DD + cg*4];
    }
    #pragma unroll
    for (int i = 0; i < 4; i++) {
        int idx = tid + i*256; int row = idx >> 4, cg = idx & 15;
        wr[i] = *(const float4*)&W[(size_t)row * DD + cg*4];
    }
    {
        unsigned st = sb;
        #pragma unroll
        for (int i = 0; i < 8; i++) {
            int idx = tid + i*256; int row = idx >> 4, cg = idx & 15;
            unsigned h0,l0,h1,l1;
            split2(xr[i].x, xr[i].y, h0, l0); split2(xr[i].z, xr[i].w, h1, l1);
            unsigned off = (unsigned)(row*144 + cg*8);
            sts64(st + off, ((unsigned long long)h1<<32)|h0);
            sts64(st + 18432 + off, ((unsigned long long)l1<<32)|l0);
        }
        #pragma unroll
        for (int i = 0; i < 4; i++) {
            int idx = tid + i*256; int row = idx >> 4, cg = idx & 15;
            unsigned h0,l0,h1,l1;
            split2(wr[i].x, wr[i].y, h0, l0); split2(wr[i].z, wr[i].w, h1, l1);
            unsigned off = (unsigned)(row*144 + cg*8);
            sts64(st + 36864 + off, ((unsigned long long)h1<<32)|h0);
            sts64(st + 46080 + off, ((unsigned long long)l1<<32)|l0);
        }
    }
    __syncthreads();

    for (int c = 0; c < 16; c++) {
        unsigned cur = sb + (unsigned)(c & 1) * STG;
        unsigned nxt = sb + (unsigned)((c + 1) & 1) * STG;
        bool more = (c < 15);
        if (more) {
            int k0 = (c + 1) * 64;
            #pragma unroll
            for (int i = 0; i < 8; i++) {
                int idx = tid + i*256; int row = idx >> 4, cg = idx & 15;
                xr[i] = *(const float4*)&Xb[(size_t)row * DD + k0 + cg*4];
            }
            #pragma unroll
            for (int i = 0; i < 4; i++) {
                int idx = tid + i*256; int row = idx >> 4, cg = idx & 15;
                wr[i] = *(const float4*)&W[(size_t)row * DD + k0 + cg*4];
            }
        }

        unsigned aBaseH = cur + (unsigned)(16*w + lrow) * 144 + lcol16;
        unsigned aBaseL = cur + 18432 + (unsigned)(16*w + lrow) * 144 + lcol16;
        #pragma unroll
        for (int ks = 0; ks < 4; ks++) {
            unsigned kb = (unsigned)ks * 32;
            unsigned aH[4], aL[4];
            ldsm4(aBaseH + kb, aH[0], aH[1], aH[2], aH[3]);
            ldsm4(aBaseL + kb, aL[0], aL[1], aL[2], aL[3]);
            unsigned bh[8][2], bl[8][2];
            #pragma unroll
            for (int nt2 = 0; nt2 < 4; nt2++) {
                unsigned r0, r1, r2, r3;
                unsigned boff = (unsigned)(nt2*16 + lrow) * 144 + lcol16 + kb;
                ldsm4(cur + 36864 + boff, r0, r1, r2, r3);
                bh[2*nt2][0] = r0; bh[2*nt2][1] = r2;
                bh[2*nt2+1][0] = r1; bh[2*nt2+1][1] = r3;
                ldsm4(cur + 46080 + boff, r0, r1, r2, r3);
                bl[2*nt2][0] = r0; bl[2*nt2][1] = r2;
                bl[2*nt2+1][0] = r1; bl[2*nt2+1][1] = r3;
            }
            #pragma unroll
            for (int nf = 0; nf < 8; nf++) {
                mma16816(cf[nf], aH, bh[nf]);
                mma16816(cf[nf], aH, bl[nf]);
                mma16816(cf[nf], aL, bh[nf]);
            }
        }

        if (more) {
            #pragma unroll
            for (int i = 0; i < 8; i++) {
                int idx = tid + i*256; int row = idx >> 4, cg = idx & 15;
                unsigned h0,l0,h1,l1;
                split2(xr[i].x, xr[i].y, h0, l0); split2(xr[i].z, xr[i].w, h1, l1);
                unsigned off = (unsigned)(row*144 + cg*8);
                sts64(nxt + off, ((unsigned long long)h1<<32)|h0);
                sts64(nxt + 18432 + off, ((unsigned long long)l1<<32)|l0);
            }
            #pragma unroll
            for (int i = 0; i < 4; i++) {
                int idx = tid + i*256; int row = idx >> 4, cg = idx & 15;
                unsigned h0,l0,h1,l1;
                split2(wr[i].x, wr[i].y, h0, l0); split2(wr[i].z, wr[i].w, h1, l1);
                unsigned off = (unsigned)(row*144 + cg*8);
                sts64(nxt + 36864 + off, ((unsigned long long)h1<<32)|h0);
                sts64(nxt + 46080 + off, ((unsigned long long)l1<<32)|l0);
            }
        }
        __syncthreads();
    }

    // epilogue
    int row0 = s0 + 16*w + (lane >> 2);
    int colb = (lane & 3) * 2;
    if (!isV) {
        #pragma unroll
        for (int nf = 0; nf < 8; nf++) {
            int col = nf * 8 + colb;
            float b0 = __ldg(&bias[col]), b1 = __ldg(&bias[col + 1]);
            unsigned h, l;
            split2(cf[nf][0] + b0, cf[nf][1] + b1, h, l);
            *(unsigned*)&dstH[(size_t)row0 * DHH + col] = h;
            *(unsigned*)&dstL[(size_t)row0 * DHH + col] = l;
            split2(cf[nf][2] + b0, cf[nf][3] + b1, h, l);
            *(unsigned*)&dstH[(size_t)(row0 + 8) * DHH + col] = h;
            *(unsigned*)&dstL[(size_t)(row0 + 8) * DHH + col] = l;
        }
    } else {
        #pragma unroll
        for (int nf = 0; nf < 8; nf++) {
            int col = nf * 8 + colb;
            float b0 = __ldg(&bias[col]), b1 = __ldg(&bias[col + 1]);
            float vv[4] = {cf[nf][0] + b0, cf[nf][1] + b1, cf[nf][2] + b0, cf[nf][3] + b1};
            int rr[4] = {row0, row0, row0 + 8, row0 + 8};
            int cc[4] = {col, col + 1, col, col + 1};
            #pragma unroll
            for (int i = 0; i < 4; i++) {
                __nv_bfloat16 hb = __float2bfloat16(vv[i]);
                __nv_bfloat16 lb = __float2bfloat16(vv[i] - __bfloat162float(hb));
                g_vT_h[((size_t)b * DHH + cc[i]) * SS + rr[i]] = hb;
                g_vT_l[((size_t)b * DHH + cc[i]) * SS + rr[i]] = lb;
            }
        }
    }
}

// ---------------- kernel 2: QK^T raw scores (HMMA, one-shot) ----------------
__global__ __launch_bounds__(256) void score_mma(float* __restrict__ attn)
{
    int x = blockIdx.x;
    int mt = (int)((sqrtf(8.f * x + 1.f) - 1.f) * 0.5f);
    while ((mt + 1) * (mt + 2) / 2 <= x) mt++;
    while (mt * (mt + 1) / 2 > x) mt--;
    int nt = x - mt * (mt + 1) / 2;
    int m0 = mt * 128, n0 = nt * 128;
    int h = blockIdx.y, b = blockIdx.z;
    int tid = threadIdx.x, w = tid >> 5, lane = tid & 31;

    extern __shared__ char sm_[];
    unsigned sb = smem_u32(sm_);
    const unsigned QH = sb, QL = sb + 18432, KH = sb + 36864, KL = sb + 55296;

    size_t bh = (size_t)(b * HH + h);
    load_bf16_pair(g_qh_h + (bh*SS + m0)*DHH, g_qh_l + (bh*SS + m0)*DHH, 128, QH, QL, tid, 256);
    load_bf16_pair(g_kh_h + (bh*SS + n0)*DHH, g_kh_l + (bh*SS + n0)*DHH, 128, KH, KL, tid, 256);
    __syncthreads();

    int mw = w >> 1, nw = w & 1;
    int lrow = lane & 15;
    unsigned lcol16 = (unsigned)(lane >> 4) * 16;

    float cf[2][8][4];
    #pragma unroll
    for (int mf = 0; mf < 2; mf++)
        #pragma unroll
        for (int nf = 0; nf < 8; nf++)
            #pragma unroll
            for (int i = 0; i < 4; i++) cf[mf][nf][i] = 0.f;

    #pragma unroll
    for (int ks = 0; ks < 4; ks++) {
        unsigned kb = (unsigned)ks * 32;
        unsigned aH[2][4], aL[2][4];
        #pragma unroll
        for (int mf = 0; mf < 2; mf++) {
            unsigned aoff = (unsigned)(mw*32 + mf*16 + lrow) * 144 + lcol16 + kb;
            ldsm4(QH + aoff, aH[mf][0], aH[mf][1], aH[mf][2], aH[mf][3]);
            ldsm4(QL + aoff, aL[mf][0], aL[mf][1], aL[mf][2], aL[mf][3]);
        }
        unsigned bh2[8][2], bl2[8][2];
        #pragma unroll
        for (int nt2 = 0; nt2 < 4; nt2++) {
            unsigned boff = (unsigned)(nw*64 + nt2*16 + lrow) * 144 + lcol16 + kb;
            unsigned r0, r1, r2, r3;
            ldsm4(KH + boff, r0, r1, r2, r3);
            bh2[2*nt2][0] = r0; bh2[2*nt2][1] = r2;
            bh2[2*nt2+1][0] = r1; bh2[2*nt2+1][1] = r3;
            ldsm4(KL + boff, r0, r1, r2, r3);
            bl2[2*nt2][0] = r0; bl2[2*nt2][1] = r2;
            bl2[2*nt2+1][0] = r1; bl2[2*nt2+1][1] = r3;
        }
        #pragma unroll
        for (int mf = 0; mf < 2; mf++)
            #pragma unroll
            for (int nf = 0; nf < 8; nf++) {
                mma16816(cf[mf][nf], aH[mf], bh2[nf]);
                mma16816(cf[mf][nf], aH[mf], bl2[nf]);
                mma16816(cf[mf][nf], aL[mf], bh2[nf]);
            }
    }

    __syncthreads();
    int rbase = mw * 32 + (lane >> 2);
    int cbase = nw * 64 + (lane & 3) * 2;
    #pragma unroll
    for (int mf = 0; mf < 2; mf++)
        #pragma unroll
        for (int nf = 0; nf < 8; nf++) {
            int r = rbase + mf * 16, c = cbase + nf * 8;
            *(float2*)(sm_ + ((size_t)r * 132 + c) * 4) = make_float2(cf[mf][nf][0], cf[mf][nf][1]);
            *(float2*)(sm_ + ((size_t)(r + 8) * 132 + c) * 4) = make_float2(cf[mf][nf][2], cf[mf][nf][3]);
        }
    __syncthreads();

    float* dstBase = attn + (((size_t)b * SS + m0) * HH + h) * SS + n0;
    #pragma unroll
    for (int i = 0; i < 16; i++) {
        int fid = (tid + i * 256) * 4;
        int row = fid >> 7, col = fid & 127;
        float4 f = *(const float4*)(sm_ + ((size_t)row * 132 + col) * 4);
        *(float4*)(dstBase + (size_t)row * HH * SS + col) = f;
    }
}

// ---------------- kernel 3: exact row softmax ----------------
__global__ __launch_bounds__(128) void softmax_k(float* __restrict__ attn)
{
    int row = blockIdx.x;
    int s = (row >> 4) & (SS - 1);
    float* p = attn + (size_t)row * SS;
    int tid = threadIdx.x;
    __shared__ float red[4];

    float vals[16];
    float mx = -INFINITY;
    #pragma unroll
    for (int i = 0; i < 4; i++) {
        int ci = i * 128 + tid;
        int t0 = ci * 4;
        if (t0 <= s) {
            float4 f = ((const float4*)p)[ci];
            float v0 = f.x*0.125f, v1 = f.y*0.125f, v2 = f.z*0.125f, v3 = f.w*0.125f;
            vals[i*4+0]=v0; vals[i*4+1]=v1; vals[i*4+2]=v2; vals[i*4+3]=v3;
            mx = fmaxf(mx, v0);
            if (t0+1 <= s) mx = fmaxf(mx, v1);
            if (t0+2 <= s) mx = fmaxf(mx, v2);
            if (t0+3 <= s) mx = fmaxf(mx, v3);
        } else {
            vals[i*4+0]=-INFINITY; vals[i*4+1]=-INFINITY;
            vals[i*4+2]=-INFINITY; vals[i*4+3]=-INFINITY;
        }
    }
    #pragma unroll
    for (int o = 16; o > 0; o >>= 1) mx = fmaxf(mx, __shfl_xor_sync(0xffffffffu, mx, o));
    if ((tid & 31) == 0) red[tid >> 5] = mx;
    __syncthreads();
    mx = fmaxf(fmaxf(red[0], red[1]), fmaxf(red[2], red[3]));
    __syncthreads();

    float sum = 0.f;
    #pragma unroll
    for (int i = 0; i < 4; i++) {
        int t0 = (i * 128 + tid) * 4;
        #pragma unroll
        for (int j = 0; j < 4; j++) {
            float e = (t0 + j <= s) ? expf(vals[i*4+j] - mx) : 0.f;
            vals[i*4+j] = e; sum += e;
        }
    }
    #pragma unroll
    for (int o = 16; o > 0; o >>= 1) sum += __shfl_xor_sync(0xffffffffu, sum, o);
    if ((tid & 31) == 0) red[tid >> 5] = sum;
    __syncthreads();
    float inv = 1.f / (red[0] + red[1] + red[2] + red[3]);

    #pragma unroll
    for (int i = 0; i < 4; i++) {
        int ci = i * 128 + tid;
        float4 o;
        o.x = vals[i*4+0]*inv; o.y = vals[i*4+1]*inv;
        o.z = vals[i*4+2]*inv; o.w = vals[i*4+3]*inv;
        ((float4*)p)[ci] = o;
    }
}

// ---------------- kernel 4: PV GEMM (HMMA, double-buffered + cp.async) ----------------
// out_h[s,e] = sum_t P[b,s,h,t] * vT[b,e,t]; block M=128, N=64, K=(mt+1)*128
__global__ __launch_bounds__(256) void pv_mma(const float* __restrict__ attn)
{
    int mt = (int)(gridDim.x - 1 - blockIdx.x);
    int h = blockIdx.y, b = blockIdx.z;
    int m0 = mt * 128;
    int tid = threadIdx.x, w = tid >> 5, lane = tid & 31;

    extern __shared__ char sm_[];
    unsigned sb = smem_u32(sm_);

    const float* P = attn + (((size_t)b * SS + m0) * HH + h) * SS;
    const __nv_bfloat16* VHs = g_vT_h + (size_t)b * DHH * SS;
    const __nv_bfloat16* VLs = g_vT_l + (size_t)b * DHH * SS;

    float cf[8][4];
    #pragma unroll
    for (int nf = 0; nf < 8; nf++)
        #pragma unroll
        for (int i = 0; i < 4; i++) cf[nf][i] = 0.f;

    int lrow = lane & 15;
    unsigned lcol16 = (unsigned)(lane >> 4) * 16;

    int nchunks = 2 * mt + 2;
    float4 pr[8];

    // prologue: chunk 0
    {
        unsigned st = sb;
        #pragma unroll
        for (int i = 0; i < 2; i++) {
            int idx = tid + i*256; int row = idx >> 3, cg = idx & 7;
            cp16(st + 36864 + (unsigned)(row*144 + cg*16), &VHs[(size_t)row * SS + cg*8]);
            cp16(st + 46080 + (unsigned)(row*144 + cg*16), &VLs[(size_t)row * SS + cg*8]);
        }
        CP_COMMIT();
        #pragma unroll
        for (int i = 0; i < 8; i++) {
            int idx = tid + i*256; int row = idx >> 4, cg = idx & 15;
            pr[i] = *(const float4*)&P[(size_t)row * (HH*SS) + cg*4];
        }
        #pragma unroll
        for (int i = 0; i < 8; i++) {
            int idx = tid + i*256; int row = idx >> 4, cg = idx & 15;
            unsigned h0,l0,h1,l1;
            split2(pr[i].x, pr[i].y, h0, l0); split2(pr[i].z, pr[i].w, h1, l1);
            unsigned off = (unsigned)(row*144 + cg*8);
            sts64(st + off, ((unsigned long long)h1<<32)|h0);
            sts64(st + 18432 + off, ((unsigned long long)l1<<32)|l0);
        }
        CP_WAIT0();
    }
    __syncthreads();

    for (int c = 0; c < nchunks; c++) {
        unsigned cur = sb + (unsigned)(c & 1) * STG;
        unsigned nxt = sb + (unsigned)((c + 1) & 1) * STG;
        bool more = (c + 1 < nchunks);
        if (more) {
            int t0 = (c + 1) * 64;
            #pragma unroll
            for (int i = 0; i < 2; i++) {
                int idx = tid + i*256; int row = idx >> 3, cg = idx & 7;
                cp16(nxt + 36864 + (unsigned)(row*144 + cg*16), &VHs[(size_t)row * SS + t0 + cg*8]);
                cp16(nxt + 46080 + (unsigned)(row*144 + cg*16), &VLs[(size_t)row * SS + t0 + cg*8]);
            }
            CP_COMMIT();
            #pragma unroll
            for (int i = 0; i < 8; i++) {
                int idx = tid + i*256; int row = idx >> 4, cg = idx & 15;
                pr[i] = *(const float4*)&P[(size_t)row * (HH*SS) + t0 + cg*4];
            }
        }

        unsigned aBaseH = cur + (unsigned)(16*w + lrow) * 144 + lcol16;
        unsigned aBaseL = cur + 18432 + (unsigned)(16*w + lrow) * 144 + lcol16;
        #pragma unroll
        for (int ks = 0; ks < 4; ks++) {
            unsigned kb = (unsigned)ks * 32;
            unsigned aH[4], aL[4];
            ldsm4(aBaseH + kb, aH[0], aH[1], aH[2], aH[3]);
            ldsm4(aBaseL + kb, aL[0], aL[1], aL[2], aL[3]);
            unsigned bh2[8][2], bl2[8][2];
            #pragma unroll
            for (int nt2 = 0; nt2 < 4; nt2++) {
                unsigned boff = (unsigned)(nt2*16 + lrow) * 144 + lcol16 + kb;
                unsigned r0, r1, r2, r3;
                ldsm4(cur + 36864 + boff, r0, r1, r2, r3);
                bh2[2*nt2][0] = r0; bh2[2*nt2][1] = r2;
                bh2[2*nt2+1][0] = r1; bh2[2*nt2+1][1] = r3;
                ldsm4(cur + 46080 + boff, r0, r1, r2, r3);
                bl2[2*nt2][0] = r0; bl2[2*nt2][1] = r2;
                bl2[2*nt2+1][0] = r1; bl2[2*nt2+1][1] = r3;
            }
            #pragma unroll
            for (int nf = 0; nf < 8; nf++) {
                mma16816(cf[nf], aH, bh2[nf]);
                mma16816(cf[nf], aH, bl2[nf]);
                mma16816(cf[nf], aL, bh2[nf]);
            }
        }

        if (more) {
            #pragma unroll
            for (int i = 0; i < 8; i++) {
                int idx = tid + i*256; int row = idx >> 4, cg = idx & 15;
                unsigned h0,l0,h1,l1;
                split2(pr[i].x, pr[i].y, h0, l0); split2(pr[i].z, pr[i].w, h1, l1);
                unsigned off = (unsigned)(row*144 + cg*8);
                sts64(nxt + off, ((unsigned long long)h1<<32)|h0);
                sts64(nxt + 18432 + off, ((unsigned long long)l1<<32)|l0);
            }
            CP_WAIT0();
        }
        __syncthreads();
    }

    int row0 = m0 + 16*w + (lane >> 2);
    int colb = (lane & 3) * 2;
    float* dst = g_oh + ((size_t)(b * HH + h) * SS) * DHH;
    #pragma unroll
    for (int nf = 0; nf < 8; nf++) {
        int col = nf * 8 + colb;
        *(float2*)&dst[(size_t)row0 * DHH + col] = make_float2(cf[nf][0], cf[nf][1]);
        *(float2*)&dst[(size_t)(row0 + 8) * DHH + col] = make_float2(cf[nf][2], cf[nf][3]);
    }
}

// ---------------- kernel 5: mean over heads ----------------
__global__ __launch_bounds__(256) void mean_kernel()
{
    int idx = blockIdx.x * 256 + threadIdx.x;
    int e = idx & 63;
    int s = (idx >> 6) & (SS - 1);
    int b = idx >> 17;
    float sum = 0.f;
    #pragma unroll
    for (int h = 0; h < HH; h++)
        sum += g_oh[((size_t)(b*HH + h)*SS + s)*DHH + e];
    g_mean[idx] = sum * (1.f / 16.f);
}

// ---------------- kernel 6: output projection ----------------
__global__ __launch_bounds__(256) void outproj_kernel(const float* __restrict__ Wo,
                                                      float* __restrict__ out)
{
    __shared__ float ms[64][68];
    __shared__ float wsm[64][68];
    int s0 = blockIdx.x * 64, d0 = blockIdx.y * 64, b = blockIdx.z;
    int tid = threadIdx.x;
    int ty = tid >> 4, tx = tid & 15;
    int lr = tid >> 2;
    int le = (tid & 3) * 16;

    #pragma unroll
    for (int i = 0; i < 16; i += 4) {
        float4 f = *(const float4*)&g_mean[((size_t)b*SS + s0+lr)*DHH + le + i];
        ms[le+i+0][lr] = f.x; ms[le+i+1][lr] = f.y;
        ms[le+i+2][lr] = f.z; ms[le+i+3][lr] = f.w;
        float4 g = *(const float4*)&Wo[(size_t)(d0+lr)*DHH + le + i];
        wsm[le+i+0][lr] = g.x; wsm[le+i+1][lr] = g.y;
        wsm[le+i+2][lr] = g.z; wsm[le+i+3][lr] = g.w;
    }
    __syncthreads();

    float acc[4][4];
    #pragma unroll
    for (int i = 0; i < 4; i++)
        #pragma unroll
        for (int j = 0; j < 4; j++) acc[i][j] = 0.f;

    #pragma unroll 16
    for (int e = 0; e < 64; e++) {
        float4 mf = *(const float4*)&ms[e][ty*4];
        float4 wf = *(const float4*)&wsm[e][tx*4];
        float mr[4] = {mf.x, mf.y, mf.z, mf.w};
        float wr[4] = {wf.x, wf.y, wf.z, wf.w};
        #pragma unroll
        for (int i = 0; i < 4; i++)
            #pragma unroll
            for (int j = 0; j < 4; j++)
                acc[i][j] += mr[i] * wr[j];
    }

    #pragma unroll
    for (int i = 0; i < 4; i++) {
        float4 o;
        o.x = acc[i][0]; o.y = acc[i][1]; o.z = acc[i][2]; o.w = acc[i][3];
        *(float4*)&out[(size_t)b*SS*DD + (size_t)(s0 + ty*4 + i)*DD + d0 + tx*4] = o;
    }
}

// ---------------- launch ----------------
extern "C" void kernel_launch(void* const* d_in, const int* in_sizes, int n_in,
                              void* d_out, int out_size)
{
    (void)in_sizes; (void)n_in; (void)out_size;
    const float* q  = (const float*)d_in[0];
    const float* k  = (const float*)d_in[1];
    const float* v  = (const float*)d_in[2];
    const float* Wv = (const float*)d_in[4];
    const float* bv = (const float*)d_in[5];
    const float* Wq = (const float*)d_in[6];
    const float* bq = (const float*)d_in[7];
    const float* Wk = (const float*)d_in[8];
    const float* bk = (const float*)d_in[9];
    const float* Wo = (const float*)d_in[10];

    float* out  = (float*)d_out;
    float* attn = out + (size_t)BB*SS*DD;

    const int PROJ_SMEM  = 2 * STG;   // 110592
    const int SCORE_SMEM = 73728;
    const int PV_SMEM    = 2 * STG;   // 110592

    cudaFuncSetAttribute(proj_mma,  cudaFuncAttributeMaxDynamicSharedMemorySize, PROJ_SMEM);
    cudaFuncSetAttribute(score_mma, cudaFuncAttributeMaxDynamicSharedMemorySize, SCORE_SMEM);
    cudaFuncSetAttribute(pv_mma,    cudaFuncAttributeMaxDynamicSharedMemorySize, PV_SMEM);

    proj_mma<<<dim3(SS/128, BB, 2*HH + 1), 256, PROJ_SMEM>>>(q, k, v, Wq, bq, Wk, bk, Wv, bv);
    score_mma<<<dim3(136, HH, BB), 256, SCORE_SMEM>>>(attn);
    softmax_k<<<BB*SS*HH, 128>>>(attn);
    pv_mma<<<dim3(SS/128, HH, BB), 256, PV_SMEM>>>(attn);
    mean_kernel<<<BB*SS*DHH/256, 256>>>();
    outproj_kernel<<<dim3(SS/64, DD/64, BB), 256>>>(Wo, out);
}

// round 9
// speedup vs baseline: 1.5269x; 1.0877x over previous
#include <cuda_runtime.h>
#include <cuda_bf16.h>
#include <math.h>

#define BB 2
#define SS 2048
#define DD 1024
#define HH 16
#define DHH 64

// ---------------- scratch ----------------
__device__ __nv_bfloat16 g_qh_h[BB*HH*SS*DHH];
__device__ __nv_bfloat16 g_qh_l[BB*HH*SS*DHH];
__device__ __nv_bfloat16 g_kh_h[BB*HH*SS*DHH];
__device__ __nv_bfloat16 g_kh_l[BB*HH*SS*DHH];
__device__ __nv_bfloat16 g_vT_h[BB*DHH*SS];   // [b, e, t]
__device__ __nv_bfloat16 g_vT_l[BB*DHH*SS];
__device__ float g_oh[BB*HH*SS*DHH];
__device__ float g_mean[BB*SS*DHH];

// ---------------- helpers ----------------
__device__ __forceinline__ unsigned smem_u32(const void* p) {
    unsigned a;
    asm("{ .reg .u64 t; cvta.to.shared.u64 t, %1; cvt.u32.u64 %0, t; }" : "=r"(a) : "l"(p));
    return a;
}

__device__ __forceinline__ void sts64(unsigned addr, unsigned long long v) {
    asm volatile("st.shared.b64 [%0], %1;" :: "r"(addr), "l"(v) : "memory");
}

__device__ __forceinline__ void ldsm4(unsigned addr, unsigned& r0, unsigned& r1,
                                      unsigned& r2, unsigned& r3) {
    asm volatile("ldmatrix.sync.aligned.m8n8.x4.shared.b16 {%0,%1,%2,%3}, [%4];"
        : "=r"(r0), "=r"(r1), "=r"(r2), "=r"(r3) : "r"(addr));
}

__device__ __forceinline__ void mma16816(float* c, const unsigned* a, const unsigned* b) {
    asm volatile("mma.sync.aligned.m16n8k16.row.col.f32.bf16.bf16.f32 "
        "{%0,%1,%2,%3}, {%4,%5,%6,%7}, {%8,%9}, {%0,%1,%2,%3};"
        : "+f"(c[0]), "+f"(c[1]), "+f"(c[2]), "+f"(c[3])
        : "r"(a[0]), "r"(a[1]), "r"(a[2]), "r"(a[3]), "r"(b[0]), "r"(b[1]));
}

__device__ __forceinline__ void split2(float a, float b, unsigned& hi, unsigned& lo) {
    __nv_bfloat162 h = __float22bfloat162_rn(make_float2(a, b));
    float2 hf = __bfloat1622float2(h);
    __nv_bfloat162 l = __float22bfloat162_rn(make_float2(a - hf.x, b - hf.y));
    hi = *(unsigned*)&h; lo = *(unsigned*)&l;
}

__device__ __forceinline__ void cp16(unsigned dst, const void* src) {
    asm volatile("cp.async.cg.shared.global [%0], [%1], 16;" :: "r"(dst), "l"(src));
}
#define CP_COMMIT() asm volatile("cp.async.commit_group;")
#define CP_WAIT0()  asm volatile("cp.async.wait_group 0;")

// rows x 64 bf16 (contiguous rows of 64) -> smem 144B rows, via cp.async
__device__ __forceinline__ void load_bf16_pair_cp(const __nv_bfloat16* __restrict__ srcH,
                                                  const __nv_bfloat16* __restrict__ srcL,
                                                  int rows, unsigned sh, unsigned sl,
                                                  int tid, int nthr) {
    int nch = rows * 8;
    for (int c = tid; c < nch; c += nthr) {
        int row = c >> 3, cg = c & 7;
        unsigned off = (unsigned)(row * 144 + cg * 16);
        cp16(sh + off, srcH + (size_t)row * 64 + cg * 8);
        cp16(sl + off, srcL + (size_t)row * 64 + cg * 8);
    }
}

#define STG 55296   // stage stride (AH 0, AL 18432, BH 36864, BL 46080)

// ---------------- kernel 1: projections (HMMA, double-buffered) ----------------
__global__ __launch_bounds__(256) void proj_mma(
    const float* __restrict__ q, const float* __restrict__ k, const float* __restrict__ v,
    const float* __restrict__ Wq, const float* __restrict__ bq,
    const float* __restrict__ Wk, const float* __restrict__ bk,
    const float* __restrict__ Wv, const float* __restrict__ bv)
{
    extern __shared__ char sm_[];
    unsigned sb = smem_u32(sm_);

    int tid = threadIdx.x, w = tid >> 5, lane = tid & 31;
    int mt = blockIdx.x, b = blockIdx.y, task = blockIdx.z;
    int s0 = mt * 128;

    const float *X, *W, *bias;
    __nv_bfloat16 *dstH = 0, *dstL = 0;
    int isV = 0;
    if (task < HH) {
        X = q + (size_t)b*SS*DD; W = Wq + (size_t)task*DHH*DD; bias = bq + task*DHH;
        dstH = g_qh_h + (size_t)(b*HH + task)*SS*DHH;
        dstL = g_qh_l + (size_t)(b*HH + task)*SS*DHH;
    } else if (task < 2*HH) {
        int h = task - HH;
        X = k + (size_t)b*SS*DD; W = Wk + (size_t)h*DHH*DD; bias = bk + h*DHH;
        dstH = g_kh_h + (size_t)(b*HH + h)*SS*DHH;
        dstL = g_kh_l + (size_t)(b*HH + h)*SS*DHH;
    } else {
        X = v + (size_t)b*SS*DD; W = Wv; bias = bv; isV = 1;
    }
    const float* Xb = X + (size_t)s0 * DD;

    float cf[8][4];
    #pragma unroll
    for (int nf = 0; nf < 8; nf++)
        #pragma unroll
        for (int i = 0; i < 4; i++) cf[nf][i] = 0.f;

    int lrow = lane & 15;
    unsigned lcol16 = (unsigned)(lane >> 4) * 16;

    float4 xr[8], wr[4];

    // prologue: load chunk 0
    #pragma unroll
    for (int i = 0; i < 8; i++) {
        int idx = tid + i*256; int row = idx >> 4, cg = idx & 15;
        xr[i] = *(const float4*)&Xb[(size_t)row * DD + cg*4];
    }
    #pragma unroll
    for (int i = 0; i < 4; i++) {
        int idx = tid + i*256; int row = idx >> 4, cg = idx & 15;
        wr[i] = *(const float4*)&W[(size_t)row * DD + cg*4];
    }
    {
        unsigned st = sb;
        #pragma unroll
        for (int i = 0; i < 8; i++) {
            int idx = tid + i*256; int row = idx >> 4, cg = idx & 15;
            unsigned h0,l0,h1,l1;
            split2(xr[i].x, xr[i].y, h0, l0); split2(xr[i].z, xr[i].w, h1, l1);
            unsigned off = (unsigned)(row*144 + cg*8);
            sts64(st + off, ((unsigned long long)h1<<32)|h0);
            sts64(st + 18432 + off, ((unsigned long long)l1<<32)|l0);
        }
        #pragma unroll
        for (int i = 0; i < 4; i++) {
            int idx = tid + i*256; int row = idx >> 4, cg = idx & 15;
            unsigned h0,l0,h1,l1;
            split2(wr[i].x, wr[i].y, h0, l0); split2(wr[i].z, wr[i].w, h1, l1);
            unsigned off = (unsigned)(row*144 + cg*8);
            sts64(st + 36864 + off, ((unsigned long long)h1<<32)|h0);
            sts64(st + 46080 + off, ((unsigned long long)l1<<32)|l0);
        }
    }
    __syncthreads();

    for (int c = 0; c < 16; c++) {
        unsigned cur = sb + (unsigned)(c & 1) * STG;
        unsigned nxt = sb + (unsigned)((c + 1) & 1) * STG;
        bool more = (c < 15);
        if (more) {
            int k0 = (c + 1) * 64;
            #pragma unroll
            for (int i = 0; i < 8; i++) {
                int idx = tid + i*256; int row = idx >> 4, cg = idx & 15;
                xr[i] = *(const float4*)&Xb[(size_t)row * DD + k0 + cg*4];
            }
            #pragma unroll
            for (int i = 0; i < 4; i++) {
                int idx = tid + i*256; int row = idx >> 4, cg = idx & 15;
                wr[i] = *(const float4*)&W[(size_t)row * DD + k0 + cg*4];
            }
        }

        unsigned aBaseH = cur + (unsigned)(16*w + lrow) * 144 + lcol16;
        unsigned aBaseL = cur + 18432 + (unsigned)(16*w + lrow) * 144 + lcol16;
        #pragma unroll
        for (int ks = 0; ks < 4; ks++) {
            unsigned kb = (unsigned)ks * 32;
            unsigned aH[4], aL[4];
            ldsm4(aBaseH + kb, aH[0], aH[1], aH[2], aH[3]);
            ldsm4(aBaseL + kb, aL[0], aL[1], aL[2], aL[3]);
            unsigned bh[8][2], bl[8][2];
            #pragma unroll
            for (int nt2 = 0; nt2 < 4; nt2++) {
                unsigned r0, r1, r2, r3;
                unsigned boff = (unsigned)(nt2*16 + lrow) * 144 + lcol16 + kb;
                ldsm4(cur + 36864 + boff, r0, r1, r2, r3);
                bh[2*nt2][0] = r0; bh[2*nt2][1] = r2;
                bh[2*nt2+1][0] = r1; bh[2*nt2+1][1] = r3;
                ldsm4(cur + 46080 + boff, r0, r1, r2, r3);
                bl[2*nt2][0] = r0; bl[2*nt2][1] = r2;
                bl[2*nt2+1][0] = r1; bl[2*nt2+1][1] = r3;
            }
            #pragma unroll
            for (int nf = 0; nf < 8; nf++) {
                mma16816(cf[nf], aH, bh[nf]);
                mma16816(cf[nf], aH, bl[nf]);
                mma16816(cf[nf], aL, bh[nf]);
            }
        }

        if (more) {
            #pragma unroll
            for (int i = 0; i < 8; i++) {
                int idx = tid + i*256; int row = idx >> 4, cg = idx & 15;
                unsigned h0,l0,h1,l1;
                split2(xr[i].x, xr[i].y, h0, l0); split2(xr[i].z, xr[i].w, h1, l1);
                unsigned off = (unsigned)(row*144 + cg*8);
                sts64(nxt + off, ((unsigned long long)h1<<32)|h0);
                sts64(nxt + 18432 + off, ((unsigned long long)l1<<32)|l0);
            }
            #pragma unroll
            for (int i = 0; i < 4; i++) {
                int idx = tid + i*256; int row = idx >> 4, cg = idx & 15;
                unsigned h0,l0,h1,l1;
                split2(wr[i].x, wr[i].y, h0, l0); split2(wr[i].z, wr[i].w, h1, l1);
                unsigned off = (unsigned)(row*144 + cg*8);
                sts64(nxt + 36864 + off, ((unsigned long long)h1<<32)|h0);
                sts64(nxt + 46080 + off, ((unsigned long long)l1<<32)|l0);
            }
        }
        __syncthreads();
    }

    // epilogue
    int row0 = s0 + 16*w + (lane >> 2);
    int colb = (lane & 3) * 2;
    if (!isV) {
        #pragma unroll
        for (int nf = 0; nf < 8; nf++) {
            int col = nf * 8 + colb;
            float b0 = __ldg(&bias[col]), b1 = __ldg(&bias[col + 1]);
            unsigned h, l;
            split2(cf[nf][0] + b0, cf[nf][1] + b1, h, l);
            *(unsigned*)&dstH[(size_t)row0 * DHH + col] = h;
            *(unsigned*)&dstL[(size_t)row0 * DHH + col] = l;
            split2(cf[nf][2] + b0, cf[nf][3] + b1, h, l);
            *(unsigned*)&dstH[(size_t)(row0 + 8) * DHH + col] = h;
            *(unsigned*)&dstL[(size_t)(row0 + 8) * DHH + col] = l;
        }
    } else {
        #pragma unroll
        for (int nf = 0; nf < 8; nf++) {
            int col = nf * 8 + colb;
            float b0 = __ldg(&bias[col]), b1 = __ldg(&bias[col + 1]);
            float vv[4] = {cf[nf][0] + b0, cf[nf][1] + b1, cf[nf][2] + b0, cf[nf][3] + b1};
            int rr[4] = {row0, row0, row0 + 8, row0 + 8};
            int cc[4] = {col, col + 1, col, col + 1};
            #pragma unroll
            for (int i = 0; i < 4; i++) {
                __nv_bfloat16 hb = __float2bfloat16(vv[i]);
                __nv_bfloat16 lb = __float2bfloat16(vv[i] - __bfloat162float(hb));
                g_vT_h[((size_t)b * DHH + cc[i]) * SS + rr[i]] = hb;
                g_vT_l[((size_t)b * DHH + cc[i]) * SS + rr[i]] = lb;
            }
        }
    }
}

// ---------------- kernel 2: QK^T raw scores (HMMA, one-shot, cp.async loads) ----------------
__global__ __launch_bounds__(256) void score_mma(float* __restrict__ attn)
{
    int x = blockIdx.x;
    int mt = (int)((sqrtf(8.f * x + 1.f) - 1.f) * 0.5f);
    while ((mt + 1) * (mt + 2) / 2 <= x) mt++;
    while (mt * (mt + 1) / 2 > x) mt--;
    int nt = x - mt * (mt + 1) / 2;
    int m0 = mt * 128, n0 = nt * 128;
    int h = blockIdx.y, b = blockIdx.z;
    int tid = threadIdx.x, w = tid >> 5, lane = tid & 31;

    extern __shared__ char sm_[];
    unsigned sb = smem_u32(sm_);
    const unsigned QH = sb, QL = sb + 18432, KH = sb + 36864, KL = sb + 55296;

    size_t bh = (size_t)(b * HH + h);
    load_bf16_pair_cp(g_qh_h + (bh*SS + m0)*DHH, g_qh_l + (bh*SS + m0)*DHH, 128, QH, QL, tid, 256);
    load_bf16_pair_cp(g_kh_h + (bh*SS + n0)*DHH, g_kh_l + (bh*SS + n0)*DHH, 128, KH, KL, tid, 256);
    CP_COMMIT();
    CP_WAIT0();
    __syncthreads();

    int mw = w >> 1, nw = w & 1;
    int lrow = lane & 15;
    unsigned lcol16 = (unsigned)(lane >> 4) * 16;

    float cf[2][8][4];
    #pragma unroll
    for (int mf = 0; mf < 2; mf++)
        #pragma unroll
        for (int nf = 0; nf < 8; nf++)
            #pragma unroll
            for (int i = 0; i < 4; i++) cf[mf][nf][i] = 0.f;

    #pragma unroll
    for (int ks = 0; ks < 4; ks++) {
        unsigned kb = (unsigned)ks * 32;
        unsigned aH[2][4], aL[2][4];
        #pragma unroll
        for (int mf = 0; mf < 2; mf++) {
            unsigned aoff = (unsigned)(mw*32 + mf*16 + lrow) * 144 + lcol16 + kb;
            ldsm4(QH + aoff, aH[mf][0], aH[mf][1], aH[mf][2], aH[mf][3]);
            ldsm4(QL + aoff, aL[mf][0], aL[mf][1], aL[mf][2], aL[mf][3]);
        }
        unsigned bh2[8][2], bl2[8][2];
        #pragma unroll
        for (int nt2 = 0; nt2 < 4; nt2++) {
            unsigned boff = (unsigned)(nw*64 + nt2*16 + lrow) * 144 + lcol16 + kb;
            unsigned r0, r1, r2, r3;
            ldsm4(KH + boff, r0, r1, r2, r3);
            bh2[2*nt2][0] = r0; bh2[2*nt2][1] = r2;
            bh2[2*nt2+1][0] = r1; bh2[2*nt2+1][1] = r3;
            ldsm4(KL + boff, r0, r1, r2, r3);
            bl2[2*nt2][0] = r0; bl2[2*nt2][1] = r2;
            bl2[2*nt2+1][0] = r1; bl2[2*nt2+1][1] = r3;
        }
        #pragma unroll
        for (int mf = 0; mf < 2; mf++)
            #pragma unroll
            for (int nf = 0; nf < 8; nf++) {
                mma16816(cf[mf][nf], aH[mf], bh2[nf]);
                mma16816(cf[mf][nf], aH[mf], bl2[nf]);
                mma16816(cf[mf][nf], aL[mf], bh2[nf]);
            }
    }

    __syncthreads();
    int rbase = mw * 32 + (lane >> 2);
    int cbase = nw * 64 + (lane & 3) * 2;
    #pragma unroll
    for (int mf = 0; mf < 2; mf++)
        #pragma unroll
        for (int nf = 0; nf < 8; nf++) {
            int r = rbase + mf * 16, c = cbase + nf * 8;
            *(float2*)(sm_ + ((size_t)r * 132 + c) * 4) = make_float2(cf[mf][nf][0], cf[mf][nf][1]);
            *(float2*)(sm_ + ((size_t)(r + 8) * 132 + c) * 4) = make_float2(cf[mf][nf][2], cf[mf][nf][3]);
        }
    __syncthreads();

    float* dstBase = attn + (((size_t)b * SS + m0) * HH + h) * SS + n0;
    #pragma unroll
    for (int i = 0; i < 16; i++) {
        int fid = (tid + i * 256) * 4;
        int row = fid >> 7, col = fid & 127;
        float4 f = *(const float4*)(sm_ + ((size_t)row * 132 + col) * 4);
        *(float4*)(dstBase + (size_t)row * HH * SS + col) = f;
    }
}

// ---------------- kernel 3: exact row softmax (masked elems never exp) ----------------
__global__ __launch_bounds__(128) void softmax_k(float* __restrict__ attn)
{
    int row = blockIdx.x;
    int s = (row >> 4) & (SS - 1);
    float* p = attn + (size_t)row * SS;
    int tid = threadIdx.x;
    __shared__ float red[4];

    float vals[16];
    float mx = -INFINITY;
    #pragma unroll
    for (int i = 0; i < 4; i++) {
        int ci = i * 128 + tid;
        int t0 = ci * 4;
        if (t0 + 3 <= s) {
            float4 f = ((const float4*)p)[ci];
            float v0 = f.x*0.125f, v1 = f.y*0.125f, v2 = f.z*0.125f, v3 = f.w*0.125f;
            vals[i*4+0]=v0; vals[i*4+1]=v1; vals[i*4+2]=v2; vals[i*4+3]=v3;
            mx = fmaxf(fmaxf(mx, fmaxf(v0, v1)), fmaxf(v2, v3));
        } else if (t0 <= s) {
            float4 f = ((const float4*)p)[ci];
            float v0 = f.x*0.125f, v1 = f.y*0.125f, v2 = f.z*0.125f, v3 = f.w*0.125f;
            vals[i*4+0]=v0; vals[i*4+1]=v1; vals[i*4+2]=v2; vals[i*4+3]=v3;
            mx = fmaxf(mx, v0);
            if (t0+1 <= s) mx = fmaxf(mx, v1);
            if (t0+2 <= s) mx = fmaxf(mx, v2);
        } else {
            vals[i*4+0]=0.f; vals[i*4+1]=0.f; vals[i*4+2]=0.f; vals[i*4+3]=0.f;
        }
    }
    #pragma unroll
    for (int o = 16; o > 0; o >>= 1) mx = fmaxf(mx, __shfl_xor_sync(0xffffffffu, mx, o));
    if ((tid & 31) == 0) red[tid >> 5] = mx;
    __syncthreads();
    mx = fmaxf(fmaxf(red[0], red[1]), fmaxf(red[2], red[3]));
    __syncthreads();

    float sum = 0.f;
    #pragma unroll
    for (int i = 0; i < 4; i++) {
        int t0 = (i * 128 + tid) * 4;
        if (t0 + 3 <= s) {
            #pragma unroll
            for (int j = 0; j < 4; j++) {
                float e = __expf(vals[i*4+j] - mx);
                vals[i*4+j] = e; sum += e;
            }
        } else if (t0 <= s) {
            #pragma unroll
            for (int j = 0; j < 4; j++) {
                if (t0 + j <= s) {
                    float e = __expf(vals[i*4+j] - mx);
                    vals[i*4+j] = e; sum += e;
                } else {
                    vals[i*4+j] = 0.f;
                }
            }
        }
        // else: already zeros, no exp issued
    }
    #pragma unroll
    for (int o = 16; o > 0; o >>= 1) sum += __shfl_xor_sync(0xffffffffu, sum, o);
    if ((tid & 31) == 0) red[tid >> 5] = sum;
    __syncthreads();
    float inv = 1.f / (red[0] + red[1] + red[2] + red[3]);

    #pragma unroll
    for (int i = 0; i < 4; i++) {
        int ci = i * 128 + tid;
        float4 o;
        o.x = vals[i*4+0]*inv; o.y = vals[i*4+1]*inv;
        o.z = vals[i*4+2]*inv; o.w = vals[i*4+3]*inv;
        ((float4*)p)[ci] = o;
    }
}

// ---------------- kernel 4: PV GEMM (HMMA, double-buffered + cp.async) ----------------
__global__ __launch_bounds__(256) void pv_mma(const float* __restrict__ attn)
{
    int mt = (int)(gridDim.x - 1 - blockIdx.x);
    int h = blockIdx.y, b = blockIdx.z;
    int m0 = mt * 128;
    int tid = threadIdx.x, w = tid >> 5, lane = tid & 31;

    extern __shared__ char sm_[];
    unsigned sb = smem_u32(sm_);

    const float* P = attn + (((size_t)b * SS + m0) * HH + h) * SS;
    const __nv_bfloat16* VHs = g_vT_h + (size_t)b * DHH * SS;
    const __nv_bfloat16* VLs = g_vT_l + (size_t)b * DHH * SS;

    float cf[8][4];
    #pragma unroll
    for (int nf = 0; nf < 8; nf++)
        #pragma unroll
        for (int i = 0; i < 4; i++) cf[nf][i] = 0.f;

    int lrow = lane & 15;
    unsigned lcol16 = (unsigned)(lane >> 4) * 16;

    int nchunks = 2 * mt + 2;
    float4 pr[8];

    // prologue: chunk 0
    {
        unsigned st = sb;
        #pragma unroll
        for (int i = 0; i < 2; i++) {
            int idx = tid + i*256; int row = idx >> 3, cg = idx & 7;
            cp16(st + 36864 + (unsigned)(row*144 + cg*16), &VHs[(size_t)row * SS + cg*8]);
            cp16(st + 46080 + (unsigned)(row*144 + cg*16), &VLs[(size_t)row * SS + cg*8]);
        }
        CP_COMMIT();
        #pragma unroll
        for (int i = 0; i < 8; i++) {
            int idx = tid + i*256; int row = idx >> 4, cg = idx & 15;
            pr[i] = *(const float4*)&P[(size_t)row * (HH*SS) + cg*4];
        }
        #pragma unroll
        for (int i = 0; i < 8; i++) {
            int idx = tid + i*256; int row = idx >> 4, cg = idx & 15;
            unsigned h0,l0,h1,l1;
            split2(pr[i].x, pr[i].y, h0, l0); split2(pr[i].z, pr[i].w, h1, l1);
            unsigned off = (unsigned)(row*144 + cg*8);
            sts64(st + off, ((unsigned long long)h1<<32)|h0);
            sts64(st + 18432 + off, ((unsigned long long)l1<<32)|l0);
        }
        CP_WAIT0();
    }
    __syncthreads();

    for (int c = 0; c < nchunks; c++) {
        unsigned cur = sb + (unsigned)(c & 1) * STG;
        unsigned nxt = sb + (unsigned)((c + 1) & 1) * STG;
        bool more = (c + 1 < nchunks);
        if (more) {
            int t0 = (c + 1) * 64;
            #pragma unroll
            for (int i = 0; i < 2; i++) {
                int idx = tid + i*256; int row = idx >> 3, cg = idx & 7;
                cp16(nxt + 36864 + (unsigned)(row*144 + cg*16), &VHs[(size_t)row * SS + t0 + cg*8]);
                cp16(nxt + 46080 + (unsigned)(row*144 + cg*16), &VLs[(size_t)row * SS + t0 + cg*8]);
            }
            CP_COMMIT();
            #pragma unroll
            for (int i = 0; i < 8; i++) {
                int idx = tid + i*256; int row = idx >> 4, cg = idx & 15;
                pr[i] = *(const float4*)&P[(size_t)row * (HH*SS) + t0 + cg*4];
            }
        }

        unsigned aBaseH = cur + (unsigned)(16*w + lrow) * 144 + lcol16;
        unsigned aBaseL = cur + 18432 + (unsigned)(16*w + lrow) * 144 + lcol16;
        #pragma unroll
        for (int ks = 0; ks < 4; ks++) {
            unsigned kb = (unsigned)ks * 32;
            unsigned aH[4], aL[4];
            ldsm4(aBaseH + kb, aH[0], aH[1], aH[2], aH[3]);
            ldsm4(aBaseL + kb, aL[0], aL[1], aL[2], aL[3]);
            unsigned bh2[8][2], bl2[8][2];
            #pragma unroll
            for (int nt2 = 0; nt2 < 4; nt2++) {
                unsigned boff = (unsigned)(nt2*16 + lrow) * 144 + lcol16 + kb;
                unsigned r0, r1, r2, r3;
                ldsm4(cur + 36864 + boff, r0, r1, r2, r3);
                bh2[2*nt2][0] = r0; bh2[2*nt2][1] = r2;
                bh2[2*nt2+1][0] = r1; bh2[2*nt2+1][1] = r3;
                ldsm4(cur + 46080 + boff, r0, r1, r2, r3);
                bl2[2*nt2][0] = r0; bl2[2*nt2][1] = r2;
                bl2[2*nt2+1][0] = r1; bl2[2*nt2+1][1] = r3;
            }
            #pragma unroll
            for (int nf = 0; nf < 8; nf++) {
                mma16816(cf[nf], aH, bh2[nf]);
                mma16816(cf[nf], aH, bl2[nf]);
                mma16816(cf[nf], aL, bh2[nf]);
            }
        }

        if (more) {
            #pragma unroll
            for (int i = 0; i < 8; i++) {
                int idx = tid + i*256; int row = idx >> 4, cg = idx & 15;
                unsigned h0,l0,h1,l1;
                split2(pr[i].x, pr[i].y, h0, l0); split2(pr[i].z, pr[i].w, h1, l1);
                unsigned off = (unsigned)(row*144 + cg*8);
                sts64(nxt + off, ((unsigned long long)h1<<32)|h0);
                sts64(nxt + 18432 + off, ((unsigned long long)l1<<32)|l0);
            }
            CP_WAIT0();
        }
        __syncthreads();
    }

    int row0 = m0 + 16*w + (lane >> 2);
    int colb = (lane & 3) * 2;
    float* dst = g_oh + ((size_t)(b * HH + h) * SS) * DHH;
    #pragma unroll
    for (int nf = 0; nf < 8; nf++) {
        int col = nf * 8 + colb;
        *(float2*)&dst[(size_t)row0 * DHH + col] = make_float2(cf[nf][0], cf[nf][1]);
        *(float2*)&dst[(size_t)(row0 + 8) * DHH + col] = make_float2(cf[nf][2], cf[nf][3]);
    }
}

// ---------------- kernel 5: mean over heads ----------------
__global__ __launch_bounds__(256) void mean_kernel()
{
    int idx = blockIdx.x * 256 + threadIdx.x;
    int e = idx & 63;
    int s = (idx >> 6) & (SS - 1);
    int b = idx >> 17;
    float sum = 0.f;
    #pragma unroll
    for (int h = 0; h < HH; h++)
        sum += g_oh[((size_t)(b*HH + h)*SS + s)*DHH + e];
    g_mean[idx] = sum * (1.f / 16.f);
}

// ---------------- kernel 6: output projection ----------------
__global__ __launch_bounds__(256) void outproj_kernel(const float* __restrict__ Wo,
                                                      float* __restrict__ out)
{
    __shared__ float ms[64][68];
    __shared__ float wsm[64][68];
    int s0 = blockIdx.x * 64, d0 = blockIdx.y * 64, b = blockIdx.z;
    int tid = threadIdx.x;
    int ty = tid >> 4, tx = tid & 15;
    int lr = tid >> 2;
    int le = (tid & 3) * 16;

    #pragma unroll
    for (int i = 0; i < 16; i += 4) {
        float4 f = *(const float4*)&g_mean[((size_t)b*SS + s0+lr)*DHH + le + i];
        ms[le+i+0][lr] = f.x; ms[le+i+1][lr] = f.y;
        ms[le+i+2][lr] = f.z; ms[le+i+3][lr] = f.w;
        float4 g = *(const float4*)&Wo[(size_t)(d0+lr)*DHH + le + i];
        wsm[le+i+0][lr] = g.x; wsm[le+i+1][lr] = g.y;
        wsm[le+i+2][lr] = g.z; wsm[le+i+3][lr] = g.w;
    }
    __syncthreads();

    float acc[4][4];
    #pragma unroll
    for (int i = 0; i < 4; i++)
        #pragma unroll
        for (int j = 0; j < 4; j++) acc[i][j] = 0.f;

    #pragma unroll 16
    for (int e = 0; e < 64; e++) {
        float4 mf = *(const float4*)&ms[e][ty*4];
        float4 wf = *(const float4*)&wsm[e][tx*4];
        float mr[4] = {mf.x, mf.y, mf.z, mf.w};
        float wr[4] = {wf.x, wf.y, wf.z, wf.w};
        #pragma unroll
        for (int i = 0; i < 4; i++)
            #pragma unroll
            for (int j = 0; j < 4; j++)
                acc[i][j] += mr[i] * wr[j];
    }

    #pragma unroll
    for (int i = 0; i < 4; i++) {
        float4 o;
        o.x = acc[i][0]; o.y = acc[i][1]; o.z = acc[i][2]; o.w = acc[i][3];
        *(float4*)&out[(size_t)b*SS*DD + (size_t)(s0 + ty*4 + i)*DD + d0 + tx*4] = o;
    }
}

// ---------------- launch ----------------
extern "C" void kernel_launch(void* const* d_in, const int* in_sizes, int n_in,
                              void* d_out, int out_size)
{
    (void)in_sizes; (void)n_in; (void)out_size;
    const float* q  = (const float*)d_in[0];
    const float* k  = (const float*)d_in[1];
    const float* v  = (const float*)d_in[2];
    const float* Wv = (const float*)d_in[4];
    const float* bv = (const float*)d_in[5];
    const float* Wq = (const float*)d_in[6];
    const float* bq = (const float*)d_in[7];
    const float* Wk = (const float*)d_in[8];
    const float* bk = (const float*)d_in[9];
    const float* Wo = (const float*)d_in[10];

    float* out  = (float*)d_out;
    float* attn = out + (size_t)BB*SS*DD;

    const int PROJ_SMEM  = 2 * STG;   // 110592
    const int SCORE_SMEM = 73728;
    const int PV_SMEM    = 2 * STG;   // 110592

    cudaFuncSetAttribute(proj_mma,  cudaFuncAttributeMaxDynamicSharedMemorySize, PROJ_SMEM);
    cudaFuncSetAttribute(score_mma, cudaFuncAttributeMaxDynamicSharedMemorySize, SCORE_SMEM);
    cudaFuncSetAttribute(pv_mma,    cudaFuncAttributeMaxDynamicSharedMemorySize, PV_SMEM);

    proj_mma<<<dim3(SS/128, BB, 2*HH + 1), 256, PROJ_SMEM>>>(q, k, v, Wq, bq, Wk, bk, Wv, bv);
    score_mma<<<dim3(136, HH, BB), 256, SCORE_SMEM>>>(attn);
    softmax_k<<<BB*SS*HH, 128>>>(attn);
    pv_mma<<<dim3(SS/128, HH, BB), 256, PV_SMEM>>>(attn);
    mean_kernel<<<BB*SS*DHH/256, 256>>>();
    outproj_kernel<<<dim3(SS/64, DD/64, BB), 256>>>(Wo, out);
}